// round 5
// baseline (speedup 1.0000x reference)
#include <cuda_runtime.h>
#include <cuda_bf16.h>
#include <cstdint>
#include <math.h>

#define B_   2
#define S_   2048
#define HID_ 2048
#define NH_  16
#define HD_  128
#define KDIM 2048

typedef __nv_bfloat16 bf16;

// ---- persistent split buffers ----
__device__ bf16 g_xh[(size_t)B_ * S_ * HID_];
__device__ bf16 g_xl[(size_t)B_ * S_ * HID_];
__device__ bf16 g_wqh[(size_t)3 * HID_ * HID_];
__device__ bf16 g_wql[(size_t)3 * HID_ * HID_];
__device__ bf16 g_woh[(size_t)HID_ * HID_];
__device__ bf16 g_wol[(size_t)HID_ * HID_];
__device__ bf16 g_qkvh[(size_t)3 * B_ * NH_ * S_ * HD_];  // [which][b][h][s][d]
__device__ bf16 g_qkvl[(size_t)3 * B_ * NH_ * S_ * HD_];
__device__ bf16 g_ctxh[(size_t)B_ * S_ * HID_];           // [b][s][h][d]
__device__ bf16 g_ctxl[(size_t)B_ * S_ * HID_];

// ---------------- helpers ----------------
__device__ __forceinline__ uint32_t s2u(const void* p) {
    return (uint32_t)__cvta_generic_to_shared(p);
}
__device__ __forceinline__ uint32_t packbf(float lo, float hi) {
    uint32_t r;
    asm("cvt.rn.bf16x2.f32 %0, %1, %2;" : "=r"(r) : "f"(hi), "f"(lo));
    return r;
}

#define MMA_BF16(d, a, b)                                                     \
    asm volatile(                                                             \
        "mma.sync.aligned.m16n8k16.row.col.f32.bf16.bf16.f32 "                \
        "{%0,%1,%2,%3}, {%4,%5,%6,%7}, {%8,%9}, {%0,%1,%2,%3};\n"             \
        : "+f"((d)[0]), "+f"((d)[1]), "+f"((d)[2]), "+f"((d)[3])              \
        : "r"((a)[0]), "r"((a)[1]), "r"((a)[2]), "r"((a)[3]),                 \
          "r"((b)[0]), "r"((b)[1]))

#define LDSM_X4(r, addr)                                                      \
    asm volatile("ldmatrix.sync.aligned.m8n8.x4.shared.b16 {%0,%1,%2,%3}, [%4];" \
                 : "=r"((r)[0]), "=r"((r)[1]), "=r"((r)[2]), "=r"((r)[3])     \
                 : "r"(addr))

#define LDSM_X4T(r, addr)                                                     \
    asm volatile("ldmatrix.sync.aligned.m8n8.x4.trans.shared.b16 {%0,%1,%2,%3}, [%4];" \
                 : "=r"((r)[0]), "=r"((r)[1]), "=r"((r)[2]), "=r"((r)[3])     \
                 : "r"(addr))

// ---------------------------------------------------------------------------
// Split fp32 -> bf16 hi/lo (prep). 4 elems/thread.
// ---------------------------------------------------------------------------
__global__ __launch_bounds__(256)
void split_kernel(const float* __restrict__ src, bf16* __restrict__ h,
                  bf16* __restrict__ l, int n4) {
    int i = blockIdx.x * 256 + threadIdx.x;
    if (i >= n4) return;
    float4 v = *(const float4*)&src[(size_t)i * 4];
    float f[4] = {v.x, v.y, v.z, v.w};
    float hf[4], lf[4];
#pragma unroll
    for (int e = 0; e < 4; e++) {
        hf[e] = __bfloat162float(__float2bfloat16(f[e]));
        lf[e] = f[e] - hf[e];
    }
    uint2 hv = make_uint2(packbf(hf[0], hf[1]), packbf(hf[2], hf[3]));
    uint2 lv = make_uint2(packbf(lf[0], lf[1]), packbf(lf[2], lf[3]));
    *(uint2*)&h[(size_t)i * 4] = hv;
    *(uint2*)&l[(size_t)i * 4] = lv;
}

// ---------------------------------------------------------------------------
// Pre-split bf16 tensor-core GEMM: C[m][n] = sum_k A[m][k]*W[n][k]
// BM=BN=128, BK=32, 256 thr, 8 warps (4Mx2N).
// MODE 0: scatter split bf16 into g_qkvh/g_qkvl.  MODE 1: fp32 out.
// ---------------------------------------------------------------------------
#define SMSTRIDE 40

template <int MODE>
__global__ __launch_bounds__(256, 2)
void gemm_bf16_kernel(const bf16* __restrict__ Agh, const bf16* __restrict__ Agl,
                      const bf16* __restrict__ Bgh, const bf16* __restrict__ Bgl,
                      float* __restrict__ Cout) {
    const int m0 = blockIdx.y * 128;
    const int n0 = blockIdx.x * 128;
    const int tid = threadIdx.x;
    const int lane = tid & 31;
    const int warp = tid >> 5;
    const int warpM = warp & 3;
    const int warpN = warp >> 2;

    __shared__ bf16 Ah[128 * SMSTRIDE];
    __shared__ bf16 Al[128 * SMSTRIDE];
    __shared__ bf16 Bh[128 * SMSTRIDE];
    __shared__ bf16 Bl[128 * SMSTRIDE];

    float C[2][8][4];
#pragma unroll
    for (int mt = 0; mt < 2; mt++)
#pragma unroll
        for (int nt = 0; nt < 8; nt++)
#pragma unroll
            for (int r = 0; r < 4; r++) C[mt][nt][r] = 0.f;

    const uint32_t uAh = s2u(Ah), uAl = s2u(Al), uBh = s2u(Bh), uBl = s2u(Bl);
    const int g = lane >> 2;
    const int qp = lane & 3;
    const int frow = lane & 15;
    const int fcol = (lane >> 4) << 3;

    for (int k0 = 0; k0 < KDIM; k0 += 32) {
        // ---- load pre-split bf16 tiles (16B vectors, no conversion) ----
#pragma unroll
        for (int t = 0; t < 2; t++) {
            int idx = tid + t * 256;        // 0..511
            int row = idx >> 2;             // 0..127
            int col = (idx & 3) * 8;        // 0,8,16,24
            size_t ga = (size_t)(m0 + row) * KDIM + k0 + col;
            size_t gb = (size_t)(n0 + row) * KDIM + k0 + col;
            *(uint4*)&Ah[row * SMSTRIDE + col] = *(const uint4*)&Agh[ga];
            *(uint4*)&Al[row * SMSTRIDE + col] = *(const uint4*)&Agl[ga];
            *(uint4*)&Bh[row * SMSTRIDE + col] = *(const uint4*)&Bgh[gb];
            *(uint4*)&Bl[row * SMSTRIDE + col] = *(const uint4*)&Bgl[gb];
        }
        __syncthreads();

#pragma unroll
        for (int kc = 0; kc < 2; kc++) {
            const int col = kc * 16 + fcol;
            uint32_t a_hi[2][4], a_lo[2][4];
#pragma unroll
            for (int mt = 0; mt < 2; mt++) {
                uint32_t off = ((warpM * 32 + mt * 16 + frow) * SMSTRIDE + col) * 2;
                LDSM_X4(a_hi[mt], uAh + off);
                LDSM_X4(a_lo[mt], uAl + off);
            }
#pragma unroll
            for (int p = 0; p < 4; p++) {
                uint32_t off = ((warpN * 64 + p * 16 + frow) * SMSTRIDE + col) * 2;
                uint32_t kb_h[4], kb_l[4];
                LDSM_X4(kb_h, uBh + off);
                LDSM_X4(kb_l, uBl + off);
                uint32_t bh0[2] = {kb_h[0], kb_h[2]};
                uint32_t bh1[2] = {kb_h[1], kb_h[3]};
                uint32_t bl0[2] = {kb_l[0], kb_l[2]};
                uint32_t bl1[2] = {kb_l[1], kb_l[3]};
#pragma unroll
                for (int mt = 0; mt < 2; mt++) {
                    MMA_BF16(C[mt][2 * p], a_hi[mt], bh0);
                    MMA_BF16(C[mt][2 * p], a_lo[mt], bh0);
                    MMA_BF16(C[mt][2 * p], a_hi[mt], bl0);
                    MMA_BF16(C[mt][2 * p + 1], a_hi[mt], bh1);
                    MMA_BF16(C[mt][2 * p + 1], a_lo[mt], bh1);
                    MMA_BF16(C[mt][2 * p + 1], a_hi[mt], bl1);
                }
            }
        }
        __syncthreads();
    }

    // epilogue
#pragma unroll
    for (int mt = 0; mt < 2; mt++) {
#pragma unroll
        for (int nt = 0; nt < 8; nt++) {
            int gm0 = m0 + warpM * 32 + mt * 16 + g;
            int gn = n0 + warpN * 64 + nt * 8 + qp * 2;
            if (MODE == 0) {
                int which = gn >> 11;
                int rem = gn & 2047;
                int h = rem >> 7;
                int d = rem & 127;
#pragma unroll
                for (int rr = 0; rr < 2; rr++) {
                    int gm = gm0 + rr * 8;
                    int b = gm >> 11;
                    int s = gm & 2047;
                    size_t off = (size_t)which * ((size_t)B_ * NH_ * S_ * HD_) +
                                 (((size_t)(b * NH_ + h)) * S_ + s) * HD_ + d;
                    float v0 = C[mt][nt][rr * 2], v1 = C[mt][nt][rr * 2 + 1];
                    float h0 = __bfloat162float(__float2bfloat16(v0));
                    float h1 = __bfloat162float(__float2bfloat16(v1));
                    *(uint32_t*)&g_qkvh[off] = packbf(h0, h1);
                    *(uint32_t*)&g_qkvl[off] = packbf(v0 - h0, v1 - h1);
                }
            } else {
                *(float2*)&Cout[(size_t)gm0 * HID_ + gn] =
                    make_float2(C[mt][nt][0], C[mt][nt][1]);
                *(float2*)&Cout[(size_t)(gm0 + 8) * HID_ + gn] =
                    make_float2(C[mt][nt][2], C[mt][nt][3]);
            }
        }
    }
}

// ---------------------------------------------------------------------------
// RoPE in-place on split Q and K halves of g_qkvh/g_qkvl.
// ---------------------------------------------------------------------------
__global__ __launch_bounds__(256)
void rope_kernel(const float* __restrict__ cosT, const float* __restrict__ sinT) {
    long long t = (long long)blockIdx.x * 256 + threadIdx.x;
    int d = (int)(t & 63);
    long long row = t >> 6;
    int s = (int)(row % S_);
    bf16* ph = g_qkvh + row * HD_;
    bf16* pl = g_qkvl + row * HD_;
    float x1 = __bfloat162float(ph[d]) + __bfloat162float(pl[d]);
    float x2 = __bfloat162float(ph[d + 64]) + __bfloat162float(pl[d + 64]);
    float c1 = cosT[s * HD_ + d];
    float s1 = sinT[s * HD_ + d];
    float c2 = cosT[s * HD_ + d + 64];
    float s2 = sinT[s * HD_ + d + 64];
    float r1 = x1 * c1 - x2 * s1;
    float r2 = x2 * c2 + x1 * s2;
    float h1 = __bfloat162float(__float2bfloat16(r1));
    float h2 = __bfloat162float(__float2bfloat16(r2));
    ph[d] = __float2bfloat16(h1);
    pl[d] = __float2bfloat16(r1 - h1);
    ph[d + 64] = __float2bfloat16(h2);
    pl[d + 64] = __float2bfloat16(r2 - h2);
}

// ---------------------------------------------------------------------------
// Split-bf16 tensor-core causal flash attention. BQ=128, BK=64, 256 threads.
// Reads pre-split q/k/v; writes pre-split ctx.
// ---------------------------------------------------------------------------
#define STQ 136
#define ATTN_SMEM ((2 * 128 + 4 * 64) * STQ * 2)   // 139264 bytes

__global__ __launch_bounds__(256, 1)
void attn_mma_kernel() {
    extern __shared__ char smraw[];
    bf16* sQh = (bf16*)smraw;
    bf16* sQl = sQh + 128 * STQ;
    bf16* sKh = sQl + 128 * STQ;
    bf16* sKl = sKh + 64 * STQ;
    bf16* sVh = sKl + 64 * STQ;
    bf16* sVl = sVh + 64 * STQ;

    const int tid = threadIdx.x;
    const int lane = tid & 31;
    const int w = tid >> 5;
    const int qp = lane & 3;
    const int g = lane >> 2;
    const int frow = lane & 15;
    const int fcol = (lane >> 4) << 3;

    const int qt = blockIdx.x;
    const int bh = blockIdx.y;
    const int b = bh >> 4;
    const int h = bh & 15;
    const int q0 = qt * 128;

    const size_t hs = (size_t)S_ * HD_;
    const bf16* Qh = g_qkvh + (size_t)bh * hs;
    const bf16* Ql = g_qkvl + (size_t)bh * hs;
    const bf16* Kh = g_qkvh + (size_t)(B_ * NH_ + bh) * hs;
    const bf16* Kl = g_qkvl + (size_t)(B_ * NH_ + bh) * hs;
    const bf16* Vh = g_qkvh + (size_t)(2 * B_ * NH_ + bh) * hs;
    const bf16* Vl = g_qkvl + (size_t)(2 * B_ * NH_ + bh) * hs;

    // ---- load Q tile (128 x 128) hi/lo ----
#pragma unroll
    for (int i = 0; i < 8; i++) {
        int idx = tid + i * 256;          // 0..2047
        int r = idx >> 4;
        int d = (idx & 15) * 8;
        size_t ga = (size_t)(q0 + r) * HD_ + d;
        *(uint4*)&sQh[r * STQ + d] = *(const uint4*)&Qh[ga];
        *(uint4*)&sQl[r * STQ + d] = *(const uint4*)&Ql[ga];
    }

    const uint32_t uQh = s2u(sQh), uQl = s2u(sQl);
    const uint32_t uKh = s2u(sKh), uKl = s2u(sKl);
    const uint32_t uVh = s2u(sVh), uVl = s2u(sVl);

    float O[16][4];
#pragma unroll
    for (int t = 0; t < 16; t++)
#pragma unroll
        for (int r = 0; r < 4; r++) O[t][r] = 0.f;
    float m0 = -1e30f, m1 = -1e30f, l0 = 0.f, l1 = 0.f;

    const float sc = 0.08838834764831845f;
    const int row0 = q0 + w * 16 + g;
    const int row1 = row0 + 8;

    __syncthreads();

    const int ktn = (q0 + 128) >> 6;
    for (int kt = 0; kt < ktn; kt++) {
        const int k0 = kt * 64;
        // ---- load K,V tiles (64 x 128 each) hi/lo ----
#pragma unroll
        for (int i = 0; i < 4; i++) {
            int idx = tid + i * 256;      // 0..1023
            int r = idx >> 4;
            int d = (idx & 15) * 8;
            size_t ga = (size_t)(k0 + r) * HD_ + d;
            *(uint4*)&sKh[r * STQ + d] = *(const uint4*)&Kh[ga];
            *(uint4*)&sKl[r * STQ + d] = *(const uint4*)&Kl[ga];
            *(uint4*)&sVh[r * STQ + d] = *(const uint4*)&Vh[ga];
            *(uint4*)&sVl[r * STQ + d] = *(const uint4*)&Vl[ga];
        }
        __syncthreads();

        const bool active = (k0 <= q0 + w * 16 + 15);
        if (active) {
            float S[8][4];
#pragma unroll
            for (int t = 0; t < 8; t++)
#pragma unroll
                for (int r = 0; r < 4; r++) S[t][r] = 0.f;

#pragma unroll
            for (int kc = 0; kc < 8; kc++) {
                const int col = kc * 16 + fcol;
                uint32_t qh[4], ql[4];
                uint32_t qoff = ((w * 16 + frow) * STQ + col) * 2;
                LDSM_X4(qh, uQh + qoff);
                LDSM_X4(ql, uQl + qoff);
#pragma unroll
                for (int p = 0; p < 4; p++) {
                    uint32_t koff = ((p * 16 + frow) * STQ + col) * 2;
                    uint32_t kh[4], kl[4];
                    LDSM_X4(kh, uKh + koff);
                    LDSM_X4(kl, uKl + koff);
                    uint32_t bh0[2] = {kh[0], kh[2]};
                    uint32_t bh1[2] = {kh[1], kh[3]};
                    uint32_t bl0[2] = {kl[0], kl[2]};
                    uint32_t bl1[2] = {kl[1], kl[3]};
                    MMA_BF16(S[2 * p], qh, bh0);
                    MMA_BF16(S[2 * p], ql, bh0);
                    MMA_BF16(S[2 * p], qh, bl0);
                    MMA_BF16(S[2 * p + 1], qh, bh1);
                    MMA_BF16(S[2 * p + 1], ql, bh1);
                    MMA_BF16(S[2 * p + 1], qh, bl1);
                }
            }

            const bool maskneed = (k0 + 63 > row0);
#pragma unroll
            for (int t = 0; t < 8; t++) {
                int c0 = k0 + 8 * t + 2 * qp;
#pragma unroll
                for (int r = 0; r < 4; r++) {
                    S[t][r] *= sc;
                    if (maskneed) {
                        int colg = c0 + (r & 1);
                        int rowg = (r < 2) ? row0 : row1;
                        if (colg > rowg) S[t][r] = -1e9f;
                    }
                }
            }

            float rm0 = -1e30f, rm1 = -1e30f;
#pragma unroll
            for (int t = 0; t < 8; t++) {
                rm0 = fmaxf(rm0, fmaxf(S[t][0], S[t][1]));
                rm1 = fmaxf(rm1, fmaxf(S[t][2], S[t][3]));
            }
            rm0 = fmaxf(rm0, __shfl_xor_sync(0xffffffffu, rm0, 1));
            rm0 = fmaxf(rm0, __shfl_xor_sync(0xffffffffu, rm0, 2));
            rm1 = fmaxf(rm1, __shfl_xor_sync(0xffffffffu, rm1, 1));
            rm1 = fmaxf(rm1, __shfl_xor_sync(0xffffffffu, rm1, 2));
            float mn0 = fmaxf(m0, rm0), mn1 = fmaxf(m1, rm1);
            float a0 = __expf(m0 - mn0), a1 = __expf(m1 - mn1);
            float rs0 = 0.f, rs1 = 0.f;
#pragma unroll
            for (int t = 0; t < 8; t++) {
                S[t][0] = __expf(S[t][0] - mn0);
                S[t][1] = __expf(S[t][1] - mn0);
                S[t][2] = __expf(S[t][2] - mn1);
                S[t][3] = __expf(S[t][3] - mn1);
                rs0 += S[t][0] + S[t][1];
                rs1 += S[t][2] + S[t][3];
            }
            rs0 += __shfl_xor_sync(0xffffffffu, rs0, 1);
            rs0 += __shfl_xor_sync(0xffffffffu, rs0, 2);
            rs1 += __shfl_xor_sync(0xffffffffu, rs1, 1);
            rs1 += __shfl_xor_sync(0xffffffffu, rs1, 2);
            l0 = l0 * a0 + rs0;
            l1 = l1 * a1 + rs1;
            m0 = mn0;
            m1 = mn1;
#pragma unroll
            for (int t = 0; t < 16; t++) {
                O[t][0] *= a0; O[t][1] *= a0;
                O[t][2] *= a1; O[t][3] *= a1;
            }

            // P fragments (hi only for P — P in [0,1], bf16 hi + lo split)
            uint32_t ph[4][4], pl[4][4];
#pragma unroll
            for (int kc2 = 0; kc2 < 4; kc2++) {
                int t0 = 2 * kc2, t1 = 2 * kc2 + 1;
                float src[8] = {S[t0][0], S[t0][1], S[t0][2], S[t0][3],
                                S[t1][0], S[t1][1], S[t1][2], S[t1][3]};
                float hv[8], lv[8];
#pragma unroll
                for (int e = 0; e < 8; e++) {
                    hv[e] = __bfloat162float(__float2bfloat16(src[e]));
                    lv[e] = src[e] - hv[e];
                }
                ph[kc2][0] = packbf(hv[0], hv[1]);
                ph[kc2][1] = packbf(hv[2], hv[3]);
                ph[kc2][2] = packbf(hv[4], hv[5]);
                ph[kc2][3] = packbf(hv[6], hv[7]);
                pl[kc2][0] = packbf(lv[0], lv[1]);
                pl[kc2][1] = packbf(lv[2], lv[3]);
                pl[kc2][2] = packbf(lv[4], lv[5]);
                pl[kc2][3] = packbf(lv[6], lv[7]);
            }

#pragma unroll
            for (int kc2 = 0; kc2 < 4; kc2++) {
#pragma unroll
                for (int p = 0; p < 8; p++) {
                    uint32_t voff = ((kc2 * 16 + frow) * STQ + p * 16 + fcol) * 2;
                    uint32_t vh[4], vl[4];
                    LDSM_X4T(vh, uVh + voff);
                    LDSM_X4T(vl, uVl + voff);
                    uint32_t bh0[2] = {vh[0], vh[1]};
                    uint32_t bh1[2] = {vh[2], vh[3]};
                    uint32_t bl0[2] = {vl[0], vl[1]};
                    uint32_t bl1[2] = {vl[2], vl[3]};
                    MMA_BF16(O[2 * p], ph[kc2], bh0);
                    MMA_BF16(O[2 * p], pl[kc2], bh0);
                    MMA_BF16(O[2 * p], ph[kc2], bl0);
                    MMA_BF16(O[2 * p + 1], ph[kc2], bh1);
                    MMA_BF16(O[2 * p + 1], pl[kc2], bh1);
                    MMA_BF16(O[2 * p + 1], ph[kc2], bl1);
                }
            }
        }
        __syncthreads();
    }

    // ---- normalize + write split ctx [b][s][h][d] ----
    float inv0 = 1.f / l0, inv1 = 1.f / l1;
    size_t base0 = (((size_t)b * S_ + row0) * NH_ + h) * HD_;
    size_t base1 = (((size_t)b * S_ + row1) * NH_ + h) * HD_;
#pragma unroll
    for (int t = 0; t < 16; t++) {
        int d = 8 * t + 2 * qp;
        float o0 = O[t][0] * inv0, o1 = O[t][1] * inv0;
        float o2 = O[t][2] * inv1, o3 = O[t][3] * inv1;
        float h0 = __bfloat162float(__float2bfloat16(o0));
        float h1 = __bfloat162float(__float2bfloat16(o1));
        float h2 = __bfloat162float(__float2bfloat16(o2));
        float h3 = __bfloat162float(__float2bfloat16(o3));
        *(uint32_t*)&g_ctxh[base0 + d] = packbf(h0, h1);
        *(uint32_t*)&g_ctxl[base0 + d] = packbf(o0 - h0, o1 - h1);
        *(uint32_t*)&g_ctxh[base1 + d] = packbf(h2, h3);
        *(uint32_t*)&g_ctxl[base1 + d] = packbf(o2 - h2, o3 - h3);
    }
}

// ---------------------------------------------------------------------------
extern "C" void kernel_launch(void* const* d_in, const int* in_sizes, int n_in,
                              void* d_out, int out_size) {
    (void)in_sizes; (void)n_in; (void)out_size;
    const float* x     = (const float*)d_in[0];
    const float* w_qkv = (const float*)d_in[1];
    const float* w_o   = (const float*)d_in[2];
    const float* cosT  = (const float*)d_in[3];
    const float* sinT  = (const float*)d_in[4];
    float* out = (float*)d_out;

    cudaFuncSetAttribute(attn_mma_kernel, cudaFuncAttributeMaxDynamicSharedMemorySize, ATTN_SMEM);

    bf16 *xh, *xl, *wqh, *wql, *woh, *wol;
    cudaGetSymbolAddress((void**)&xh, g_xh);
    cudaGetSymbolAddress((void**)&xl, g_xl);
    cudaGetSymbolAddress((void**)&wqh, g_wqh);
    cudaGetSymbolAddress((void**)&wql, g_wql);
    cudaGetSymbolAddress((void**)&woh, g_woh);
    cudaGetSymbolAddress((void**)&wol, g_wol);
    bf16 *ctxh, *ctxl;
    cudaGetSymbolAddress((void**)&ctxh, g_ctxh);
    cudaGetSymbolAddress((void**)&ctxl, g_ctxl);

    // 0) pre-split inputs
    int n4x = (B_ * S_ * HID_) / 4;
    int n4q = (3 * HID_ * HID_) / 4;
    int n4o = (HID_ * HID_) / 4;
    split_kernel<<<(n4x + 255) / 256, 256>>>(x, xh, xl, n4x);
    split_kernel<<<(n4q + 255) / 256, 256>>>(w_qkv, wqh, wql, n4q);
    split_kernel<<<(n4o + 255) / 256, 256>>>(w_o, woh, wol, n4o);

    // 1) QKV projection
    gemm_bf16_kernel<0><<<dim3(6144 / 128, 4096 / 128), 256>>>(xh, xl, wqh, wql, nullptr);

    // 2) RoPE
    rope_kernel<<<(2 * B_ * NH_ * S_ * 64) / 256, 256>>>(cosT, sinT);

    // 3) Flash attention
    attn_mma_kernel<<<dim3(S_ / 128, B_ * NH_), 256, ATTN_SMEM>>>();

    // 4) Output projection
    gemm_bf16_kernel<1><<<dim3(2048 / 128, 4096 / 128), 256>>>(ctxh, ctxl, woh, wol, out);
}